// round 15
// baseline (speedup 1.0000x reference)
#include <cuda_runtime.h>
#include <cuda_bf16.h>
#include <cstdint>

#define BATCH 4096
#define DIM 128
#define NROWS (2 * BATCH)            // 8192
#define BM 128
#define BN 128
#define NBLK (NROWS / BM)            // 64 row/col blocks
#define NT_TOTAL (NBLK * (NBLK + 1) / 2)  // 2080 upper-triangle tiles
#define NCTA 148
#define NRBLK 16                     // rowterm grid
#define NTHR 512

#define STRB 272                     // smem tile row stride in bytes (136 bf16)
#define SM_A0 0
#define SM_B0 34816
#define SM_A1 69632
#define SM_B1 104448
#define SM_REDR 139264               // 512 floats (row partials x 4 wn)
#define SM_REDC 141312               // 128*33 floats (col slot partials)
#define SM_TOTAL (SM_REDC + 128 * 33 * 4)  // 158208 bytes

// Scratch (device globals; no allocation allowed)
__device__ __align__(16) __nv_bfloat16 gx_reps[NROWS * DIM]; // normalized rows, bf16
__device__ float gx_pos[BATCH];               // exact fp32 dot(z_i, z_j)
__device__ float gx_slice[NCTA * NROWS];      // per-CTA exp-rowsum slices
__device__ float gx_bsum[NRBLK];              // rowterm block partials
__device__ int   gx_ctr;                      // last-block ticket (self-resetting)

// ---------------------------------------------------------------------------
// helpers
// ---------------------------------------------------------------------------
__device__ __forceinline__ uint32_t smem_cast_u32(const void* p) {
    uint32_t a;
    asm("{ .reg .u64 t; cvta.to.shared.u64 t, %1; cvt.u32.u64 %0, t; }"
        : "=r"(a) : "l"(p));
    return a;
}

__device__ __forceinline__ void ldsm_x4(uint32_t* r, uint32_t addr) {
    asm volatile("ldmatrix.sync.aligned.m8n8.x4.shared.b16 {%0,%1,%2,%3}, [%4];"
                 : "=r"(r[0]), "=r"(r[1]), "=r"(r[2]), "=r"(r[3]) : "r"(addr));
}

__device__ __forceinline__ void mma_bf16_16816(float* c, const uint32_t* a,
                                               uint32_t b0, uint32_t b1) {
    asm volatile(
        "mma.sync.aligned.m16n8k16.row.col.f32.bf16.bf16.f32 "
        "{%0,%1,%2,%3}, {%4,%5,%6,%7}, {%8,%9}, {%0,%1,%2,%3};"
        : "+f"(c[0]), "+f"(c[1]), "+f"(c[2]), "+f"(c[3])
        : "r"(a[0]), "r"(a[1]), "r"(a[2]), "r"(a[3]), "r"(b0), "r"(b1));
}

// Map linear upper-triangle index -> (i, j), i <= j.  off(i) = i*(129-i)/2.
__device__ __forceinline__ void tri_index_map(int idx, int& io, int& jo) {
    float f = (129.0f - sqrtf(16641.0f - 8.0f * (float)idx)) * 0.5f;
    int i = (int)f;
    while (i > 0 && i * (129 - i) / 2 > idx) --i;
    while ((i + 1) * (128 - i) / 2 <= idx) ++i;
    io = i;
    jo = i + (idx - i * (129 - i) / 2);
}

// Prefetch tile pair (A = block i, B = block j) into buffer parity p.
__device__ __forceinline__ void prefetch_tiles(uint32_t sb, int p, int i, int j, int tid) {
    uint32_t abuf = sb + (p ? SM_A1 : SM_A0);
    uint32_t bbuf = sb + (p ? SM_B1 : SM_B0);
    const char* ga = (const char*)(gx_reps + (size_t)i * BM * DIM);
    const char* gb = (const char*)(gx_reps + (size_t)j * BN * DIM);
#pragma unroll
    for (int it = 0; it < 4; ++it) {
        int idx2 = tid + it * NTHR;      // 0..2047 (16B chunks)
        int r = idx2 >> 4, s = idx2 & 15;
        uint32_t off = (uint32_t)(r * STRB + s * 16);
        const char* g0 = ga + r * 256 + s * 16;
        const char* g1 = gb + r * 256 + s * 16;
        asm volatile("cp.async.cg.shared.global [%0], [%1], 16;"
                     :: "r"(abuf + off), "l"(g0));
        asm volatile("cp.async.cg.shared.global [%0], [%1], 16;"
                     :: "r"(bbuf + off), "l"(g1));
    }
}

// ---------------------------------------------------------------------------
// Kernel 1: normalize both projections -> bf16 reps; exact fp32 positives.
// Warp-per-row, float4 loads, bf16x2 vector stores.
// ---------------------------------------------------------------------------
__global__ void __launch_bounds__(256) l2norm_pos_kernel(const float* __restrict__ p1,
                                                         const float* __restrict__ p2) {
    int w = threadIdx.x >> 5;
    int lane = threadIdx.x & 31;
    int b = blockIdx.x * 8 + w;                  // row 0..4095
    const float4* r1 = (const float4*)(p1 + (size_t)b * DIM);
    const float4* r2 = (const float4*)(p2 + (size_t)b * DIM);
    float4 v1 = r1[lane];
    float4 v2 = r2[lane];
    float s11 = v1.x * v1.x + v1.y * v1.y + v1.z * v1.z + v1.w * v1.w;
    float s22 = v2.x * v2.x + v2.y * v2.y + v2.z * v2.z + v2.w * v2.w;
    float s12 = v1.x * v2.x + v1.y * v2.y + v1.z * v2.z + v1.w * v2.w;
#pragma unroll
    for (int o = 16; o > 0; o >>= 1) {
        s11 += __shfl_xor_sync(0xffffffffu, s11, o);
        s22 += __shfl_xor_sync(0xffffffffu, s22, o);
        s12 += __shfl_xor_sync(0xffffffffu, s12, o);
    }
    float n1 = fmaxf(sqrtf(s11), 1e-12f);
    float n2 = fmaxf(sqrtf(s22), 1e-12f);
    float in1 = 1.0f / n1, in2 = 1.0f / n2;
    __nv_bfloat162 o1a = __floats2bfloat162_rn(v1.x * in1, v1.y * in1);
    __nv_bfloat162 o1b = __floats2bfloat162_rn(v1.z * in1, v1.w * in1);
    __nv_bfloat162 o2a = __floats2bfloat162_rn(v2.x * in2, v2.y * in2);
    __nv_bfloat162 o2b = __floats2bfloat162_rn(v2.z * in2, v2.w * in2);
    uint2* d1 = (uint2*)(gx_reps + (size_t)b * DIM);
    uint2* d2 = (uint2*)(gx_reps + (size_t)(BATCH + b) * DIM);
    uint2 u1, u2;
    u1.x = *(uint32_t*)&o1a; u1.y = *(uint32_t*)&o1b;
    u2.x = *(uint32_t*)&o2a; u2.y = *(uint32_t*)&o2b;
    d1[lane] = u1;
    d2[lane] = u2;
    if (lane == 0) gx_pos[b] = s12 * in1 * in2;
}

// ---------------------------------------------------------------------------
// Kernel 2: persistent symmetric warp-mma sim + fused exp row/col sums.
// NOW 512 threads: 16 warps in 4(m) x 4(n); warp tile 32x32 -> 4 warps per
// SMSP so exp/reduce of one warp overlaps MMA of another (R14 showed the
// 256-thread version ran at ~2x its pipe-work floor from exposed latency).
// Reduction mappings identical in structure to the validated R13/R14 kernel.
// ---------------------------------------------------------------------------
extern __shared__ char smbuf[];

__global__ void __launch_bounds__(NTHR, 1) simexp_tri_kernel() {
    const uint32_t sb = smem_cast_u32(smbuf);
    const int tid = threadIdx.x;
    const int lane = tid & 31;
    const int wid = tid >> 5;
    const int wm = wid & 3;          // m chunk (32 rows)
    const int wn = wid >> 2;         // n chunk (32 cols)
    const int cta = blockIdx.x;
    float* slice = gx_slice + (size_t)cta * NROWS;
    float* red_r = (float*)(smbuf + SM_REDR);
    float* red_c2 = (float*)(smbuf + SM_REDC);

    // zero this CTA's slice
    for (int k = tid; k < NROWS; k += NTHR) slice[k] = 0.f;

    const int lrow = lane & 15;
    const int lcol = (lane >> 4) * 16;
    const int slot = wm * 8 + (lane >> 2);   // unique row-slot for colsum cells

    int idx = cta;
    int i, j;
    tri_index_map(idx, i, j);
    prefetch_tiles(sb, 0, i, j, tid);
    asm volatile("cp.async.commit_group;" ::: "memory");

    int p = 0;
    for (; idx < NT_TOTAL; idx += NCTA, p ^= 1) {
        int ni = 0, nj = 0;
        const bool has_next = (idx + NCTA < NT_TOTAL);
        if (has_next) {
            tri_index_map(idx + NCTA, ni, nj);
            prefetch_tiles(sb, p ^ 1, ni, nj, tid);
            asm volatile("cp.async.commit_group;" ::: "memory");
            asm volatile("cp.async.wait_group 1;" ::: "memory");
        } else {
            asm volatile("cp.async.wait_group 0;" ::: "memory");
        }
        __syncthreads();   // tile ready; also guards red_r/red_c2 reuse

        const uint32_t a_base = sb + (p ? SM_A1 : SM_A0)
                              + (uint32_t)(wm * 32 + lrow) * STRB + lcol;
        const uint32_t b_base = sb + (p ? SM_B1 : SM_B0)
                              + (uint32_t)(wn * 32 + lrow) * STRB + lcol;

        float acc[2][4][4];
#pragma unroll
        for (int m = 0; m < 2; ++m)
#pragma unroll
            for (int n = 0; n < 4; ++n)
#pragma unroll
                for (int q = 0; q < 4; ++q) acc[m][n][q] = 0.f;

#pragma unroll
        for (int ks = 0; ks < 8; ++ks) {
            uint32_t a[2][4];
            ldsm_x4(a[0], a_base + ks * 32);
            ldsm_x4(a[1], a_base + 16 * STRB + ks * 32);
#pragma unroll
            for (int pp = 0; pp < 2; ++pp) {
                uint32_t b[4];
                ldsm_x4(b, b_base + (uint32_t)(pp * 16) * STRB + ks * 32);
#pragma unroll
                for (int mt = 0; mt < 2; ++mt) {
                    mma_bf16_16816(acc[mt][2 * pp],     a[mt], b[0], b[2]);
                    mma_bf16_16816(acc[mt][2 * pp + 1], a[mt], b[1], b[3]);
                }
            }
        }

        // exps in place
#pragma unroll
        for (int mt = 0; mt < 2; ++mt)
#pragma unroll
            for (int nt = 0; nt < 4; ++nt)
#pragma unroll
                for (int q = 0; q < 4; ++q)
                    acc[mt][nt][q] = __expf(2.f * acc[mt][nt][q]);

        // rowsum: reduce along n (cols) -> 4 row values/thread
        float rowsum[4] = {0.f, 0.f, 0.f, 0.f};
#pragma unroll
        for (int mt = 0; mt < 2; ++mt)
#pragma unroll
            for (int nt = 0; nt < 4; ++nt) {
                rowsum[mt * 2 + 0] += acc[mt][nt][0] + acc[mt][nt][1];
                rowsum[mt * 2 + 1] += acc[mt][nt][2] + acc[mt][nt][3];
            }
#pragma unroll
        for (int r2 = 0; r2 < 4; ++r2) {
            rowsum[r2] += __shfl_xor_sync(0xffffffffu, rowsum[r2], 1);
            rowsum[r2] += __shfl_xor_sync(0xffffffffu, rowsum[r2], 2);
        }
        if ((lane & 3) == 0) {
#pragma unroll
            for (int r2 = 0; r2 < 4; ++r2) {
                int row = wm * 32 + (r2 >> 1) * 16 + (r2 & 1) * 8 + (lane >> 2);
                red_r[row * 4 + wn] = rowsum[r2];
            }
        }

        // colsum (skip on diag): fold the 4 same-column accumulators
        // (rows +0/+8/+16/+24 relative to lane>>2) and store to a unique cell.
        if (i != j) {
#pragma unroll
            for (int nt = 0; nt < 4; ++nt) {
#pragma unroll
                for (int j0 = 0; j0 < 2; ++j0) {
                    float v = acc[0][nt][j0] + acc[0][nt][j0 + 2]
                            + acc[1][nt][j0] + acc[1][nt][j0 + 2];
                    int col = wn * 32 + (nt >> 1) * 16 + (nt & 1) * 8
                            + (lane & 3) * 2 + j0;
                    red_c2[col * 33 + slot] = v;
                }
            }
        }
        __syncthreads();

        if (tid < BM) {
            slice[i * BM + tid] += red_r[tid * 4 + 0] + red_r[tid * 4 + 1]
                                 + red_r[tid * 4 + 2] + red_r[tid * 4 + 3];
            if (i != j) {
                float s = 0.f;
#pragma unroll
                for (int k = 0; k < 32; ++k) s += red_c2[tid * 33 + k];
                slice[j * BN + tid] += s;
            }
        }

        // advance tile coordinates
        i = ni;
        j = nj;
    }
}

// ---------------------------------------------------------------------------
// Kernel 3: per-row term + block reduce + last-block finalize (fused mean).
// Deterministic: the last block reads the fixed 16-element partial array in
// fixed order; the ticket counter self-resets for graph replay.
// ---------------------------------------------------------------------------
__global__ void __launch_bounds__(512) rowterm_final_kernel(float* __restrict__ out) {
    const float E2 = 7.38905609893065f;  // exp(2): diagonal of normalized sim
    int tid = threadIdx.x;
    int r = blockIdx.x * 512 + tid;
    float s = 0.f;
#pragma unroll 4
    for (int c = 0; c < NCTA; ++c) s += gx_slice[(size_t)c * NROWS + r];
    float term = logf(s - E2) - 2.0f * gx_pos[r & (BATCH - 1)];
#pragma unroll
    for (int o = 16; o > 0; o >>= 1)
        term += __shfl_xor_sync(0xffffffffu, term, o);
    __shared__ float sh[16];
    __shared__ bool is_last;
    if ((tid & 31) == 0) sh[tid >> 5] = term;
    __syncthreads();
    if (tid < 32) {
        float v = (tid < 16) ? sh[tid] : 0.f;
#pragma unroll
        for (int o = 8; o > 0; o >>= 1) v += __shfl_xor_sync(0xffffffffu, v, o);
        if (tid == 0) {
            gx_bsum[blockIdx.x] = v;
            __threadfence();
            int old = atomicAdd(&gx_ctr, 1);
            is_last = (old == NRBLK - 1);
        }
    }
    __syncthreads();
    if (is_last && tid < 32) {
        __threadfence();
        float v = (tid < NRBLK) ? gx_bsum[tid] : 0.f;
#pragma unroll
        for (int o = 8; o > 0; o >>= 1) v += __shfl_xor_sync(0xffffffffu, v, o);
        if (tid == 0) {
            out[0] = v * (1.0f / (float)NROWS);
            gx_ctr = 0;  // reset for next graph replay
        }
    }
}

// ---------------------------------------------------------------------------
extern "C" void kernel_launch(void* const* d_in, const int* in_sizes, int n_in,
                              void* d_out, int out_size) {
    const float* p1 = (const float*)d_in[0];
    const float* p2 = (const float*)d_in[1];
    float* out = (float*)d_out;

    l2norm_pos_kernel<<<BATCH / 8, 256>>>(p1, p2);

    cudaFuncSetAttribute((const void*)simexp_tri_kernel,
                         cudaFuncAttributeMaxDynamicSharedMemorySize, SM_TOTAL);
    simexp_tri_kernel<<<NCTA, NTHR, SM_TOTAL>>>();

    rowterm_final_kernel<<<NRBLK, 512>>>(out);
}

// round 17
// speedup vs baseline: 1.0279x; 1.0279x over previous
#include <cuda_runtime.h>
#include <cuda_bf16.h>
#include <cstdint>

#define BATCH 4096
#define DIM 128
#define NROWS (2 * BATCH)            // 8192
#define BM 128
#define BN 128
#define NBLK (NROWS / BM)            // 64 row/col blocks
#define NT_TOTAL (NBLK * (NBLK + 1) / 2)  // 2080 upper-triangle tiles
#define NCTA 148
#define NRBLK 16                     // rowterm grid

#define STRB 272                     // smem tile row stride in bytes (136 bf16)
#define SM_A0 0
#define SM_B0 34816
#define SM_A1 69632
#define SM_B1 104448
#define SM_REDR 139264               // 256 floats (row partials x 2 wn)
#define SM_REDC 140288               // 128*33 floats (col slot partials)
#define SM_TOTAL (SM_REDC + 128 * 33 * 4)  // 157184 bytes

// Scratch (device globals; no allocation allowed)
__device__ __align__(16) __nv_bfloat16 gx_reps[NROWS * DIM]; // normalized rows, bf16
__device__ float gx_pos[BATCH];               // exact fp32 dot(z_i, z_j)
__device__ float gx_slice[NCTA * NROWS];      // per-CTA exp-rowsum slices
__device__ float gx_bsum[NRBLK];              // rowterm block partials
__device__ int   gx_ctr;                      // last-block ticket (self-resetting)

// ---------------------------------------------------------------------------
// helpers
// ---------------------------------------------------------------------------
__device__ __forceinline__ uint32_t smem_cast_u32(const void* p) {
    uint32_t a;
    asm("{ .reg .u64 t; cvta.to.shared.u64 t, %1; cvt.u32.u64 %0, t; }"
        : "=r"(a) : "l"(p));
    return a;
}

__device__ __forceinline__ void ldsm_x4(uint32_t* r, uint32_t addr) {
    asm volatile("ldmatrix.sync.aligned.m8n8.x4.shared.b16 {%0,%1,%2,%3}, [%4];"
                 : "=r"(r[0]), "=r"(r[1]), "=r"(r[2]), "=r"(r[3]) : "r"(addr));
}

__device__ __forceinline__ void mma_bf16_16816(float* c, const uint32_t* a,
                                               uint32_t b0, uint32_t b1) {
    asm volatile(
        "mma.sync.aligned.m16n8k16.row.col.f32.bf16.bf16.f32 "
        "{%0,%1,%2,%3}, {%4,%5,%6,%7}, {%8,%9}, {%0,%1,%2,%3};"
        : "+f"(c[0]), "+f"(c[1]), "+f"(c[2]), "+f"(c[3])
        : "r"(a[0]), "r"(a[1]), "r"(a[2]), "r"(a[3]), "r"(b0), "r"(b1));
}

// Map linear upper-triangle index -> (i, j), i <= j.  off(i) = i*(129-i)/2.
__device__ __forceinline__ void tri_index_map(int idx, int& io, int& jo) {
    float f = (129.0f - sqrtf(16641.0f - 8.0f * (float)idx)) * 0.5f;
    int i = (int)f;
    while (i > 0 && i * (129 - i) / 2 > idx) --i;
    while ((i + 1) * (128 - i) / 2 <= idx) ++i;
    io = i;
    jo = i + (idx - i * (129 - i) / 2);
}

// Prefetch tile pair (A = block i, B = block j) into buffer parity p.
__device__ __forceinline__ void prefetch_tiles(uint32_t sb, int p, int i, int j, int tid) {
    uint32_t abuf = sb + (p ? SM_A1 : SM_A0);
    uint32_t bbuf = sb + (p ? SM_B1 : SM_B0);
    const char* ga = (const char*)(gx_reps + (size_t)i * BM * DIM);
    const char* gb = (const char*)(gx_reps + (size_t)j * BN * DIM);
#pragma unroll
    for (int it = 0; it < 8; ++it) {
        int idx2 = tid + it * 256;       // 0..2047 (16B chunks)
        int r = idx2 >> 4, s = idx2 & 15;
        uint32_t off = (uint32_t)(r * STRB + s * 16);
        const char* g0 = ga + r * 256 + s * 16;
        const char* g1 = gb + r * 256 + s * 16;
        asm volatile("cp.async.cg.shared.global [%0], [%1], 16;"
                     :: "r"(abuf + off), "l"(g0));
        asm volatile("cp.async.cg.shared.global [%0], [%1], 16;"
                     :: "r"(bbuf + off), "l"(g1));
    }
}

// ---------------------------------------------------------------------------
// Kernel 1: normalize both projections -> bf16 reps; exact fp32 positives.
// Warp-per-row, float4 loads, bf16x2 vector stores.
// ---------------------------------------------------------------------------
__global__ void __launch_bounds__(256) l2norm_pos_kernel(const float* __restrict__ p1,
                                                         const float* __restrict__ p2) {
    int w = threadIdx.x >> 5;
    int lane = threadIdx.x & 31;
    int b = blockIdx.x * 8 + w;                  // row 0..4095
    const float4* r1 = (const float4*)(p1 + (size_t)b * DIM);
    const float4* r2 = (const float4*)(p2 + (size_t)b * DIM);
    float4 v1 = r1[lane];
    float4 v2 = r2[lane];
    float s11 = v1.x * v1.x + v1.y * v1.y + v1.z * v1.z + v1.w * v1.w;
    float s22 = v2.x * v2.x + v2.y * v2.y + v2.z * v2.z + v2.w * v2.w;
    float s12 = v1.x * v2.x + v1.y * v2.y + v1.z * v2.z + v1.w * v2.w;
#pragma unroll
    for (int o = 16; o > 0; o >>= 1) {
        s11 += __shfl_xor_sync(0xffffffffu, s11, o);
        s22 += __shfl_xor_sync(0xffffffffu, s22, o);
        s12 += __shfl_xor_sync(0xffffffffu, s12, o);
    }
    float n1 = fmaxf(sqrtf(s11), 1e-12f);
    float n2 = fmaxf(sqrtf(s22), 1e-12f);
    float in1 = 1.0f / n1, in2 = 1.0f / n2;
    __nv_bfloat162 o1a = __floats2bfloat162_rn(v1.x * in1, v1.y * in1);
    __nv_bfloat162 o1b = __floats2bfloat162_rn(v1.z * in1, v1.w * in1);
    __nv_bfloat162 o2a = __floats2bfloat162_rn(v2.x * in2, v2.y * in2);
    __nv_bfloat162 o2b = __floats2bfloat162_rn(v2.z * in2, v2.w * in2);
    uint2* d1 = (uint2*)(gx_reps + (size_t)b * DIM);
    uint2* d2 = (uint2*)(gx_reps + (size_t)(BATCH + b) * DIM);
    uint2 u1, u2;
    u1.x = *(uint32_t*)&o1a; u1.y = *(uint32_t*)&o1b;
    u2.x = *(uint32_t*)&o2a; u2.y = *(uint32_t*)&o2b;
    d1[lane] = u1;
    d2[lane] = u2;
    if (lane == 0) gx_pos[b] = s12 * in1 * in2;
}

// ---------------------------------------------------------------------------
// Kernel 2: persistent symmetric warp-mma sim + fused exp row/col sums.
// EXACT R14 winner configuration: 256 threads, 8 warps in 4(m) x 2(n),
// warp tile 32x64 (R15 proved 32x32/512thr regresses: +33% LDSM, half the
// per-warp MMA reuse). Validated at rel_err 0.0 / 62.0us.
// ---------------------------------------------------------------------------
extern __shared__ char smbuf[];

__global__ void __launch_bounds__(256, 1) simexp_tri_kernel() {
    const uint32_t sb = smem_cast_u32(smbuf);
    const int tid = threadIdx.x;
    const int lane = tid & 31;
    const int wid = tid >> 5;
    const int wm = wid & 3;          // m chunk (32 rows)
    const int wn = wid >> 2;         // n chunk (64 cols)
    const int cta = blockIdx.x;
    float* slice = gx_slice + (size_t)cta * NROWS;
    float* red_r = (float*)(smbuf + SM_REDR);
    float* red_c2 = (float*)(smbuf + SM_REDC);

    // zero this CTA's slice
    for (int k = tid; k < NROWS; k += 256) slice[k] = 0.f;

    const int lrow = lane & 15;
    const int lcol = (lane >> 4) * 16;
    const int slot = wm * 8 + (lane >> 2);   // unique row-slot for colsum cells

    int idx = cta;
    int i, j;
    tri_index_map(idx, i, j);
    prefetch_tiles(sb, 0, i, j, tid);
    asm volatile("cp.async.commit_group;" ::: "memory");

    int p = 0;
    for (; idx < NT_TOTAL; idx += NCTA, p ^= 1) {
        int ni = 0, nj = 0;
        const bool has_next = (idx + NCTA < NT_TOTAL);
        if (has_next) {
            tri_index_map(idx + NCTA, ni, nj);
            prefetch_tiles(sb, p ^ 1, ni, nj, tid);
            asm volatile("cp.async.commit_group;" ::: "memory");
            asm volatile("cp.async.wait_group 1;" ::: "memory");
        } else {
            asm volatile("cp.async.wait_group 0;" ::: "memory");
        }
        __syncthreads();   // tile ready; also guards red_r/red_c2 reuse

        const uint32_t a_base = sb + (p ? SM_A1 : SM_A0)
                              + (uint32_t)(wm * 32 + lrow) * STRB + lcol;
        const uint32_t b_base = sb + (p ? SM_B1 : SM_B0)
                              + (uint32_t)(wn * 64 + lrow) * STRB + lcol;

        float acc[2][8][4];
#pragma unroll
        for (int m = 0; m < 2; ++m)
#pragma unroll
            for (int n = 0; n < 8; ++n)
#pragma unroll
                for (int q = 0; q < 4; ++q) acc[m][n][q] = 0.f;

#pragma unroll
        for (int ks = 0; ks < 8; ++ks) {
            uint32_t a[2][4];
            ldsm_x4(a[0], a_base + ks * 32);
            ldsm_x4(a[1], a_base + 16 * STRB + ks * 32);
#pragma unroll
            for (int pp = 0; pp < 4; ++pp) {
                uint32_t b[4];
                ldsm_x4(b, b_base + (uint32_t)(pp * 16) * STRB + ks * 32);
#pragma unroll
                for (int mt = 0; mt < 2; ++mt) {
                    mma_bf16_16816(acc[mt][2 * pp],     a[mt], b[0], b[2]);
                    mma_bf16_16816(acc[mt][2 * pp + 1], a[mt], b[1], b[3]);
                }
            }
        }

        // exps in place
#pragma unroll
        for (int mt = 0; mt < 2; ++mt)
#pragma unroll
            for (int nt = 0; nt < 8; ++nt)
#pragma unroll
                for (int q = 0; q < 4; ++q)
                    acc[mt][nt][q] = __expf(2.f * acc[mt][nt][q]);

        // rowsum: reduce along n (cols) -> 4 row values/thread
        float rowsum[4] = {0.f, 0.f, 0.f, 0.f};
#pragma unroll
        for (int mt = 0; mt < 2; ++mt)
#pragma unroll
            for (int nt = 0; nt < 8; ++nt) {
                rowsum[mt * 2 + 0] += acc[mt][nt][0] + acc[mt][nt][1];
                rowsum[mt * 2 + 1] += acc[mt][nt][2] + acc[mt][nt][3];
            }
#pragma unroll
        for (int r2 = 0; r2 < 4; ++r2) {
            rowsum[r2] += __shfl_xor_sync(0xffffffffu, rowsum[r2], 1);
            rowsum[r2] += __shfl_xor_sync(0xffffffffu, rowsum[r2], 2);
        }
        if ((lane & 3) == 0) {
#pragma unroll
            for (int r2 = 0; r2 < 4; ++r2) {
                int row = wm * 32 + (r2 >> 1) * 16 + (r2 & 1) * 8 + (lane >> 2);
                red_r[row * 2 + wn] = rowsum[r2];
            }
        }

        // colsum (skip on diag): fold the 4 same-column accumulators
        // (rows +0/+8/+16/+24 relative to lane>>2) and store to a unique cell.
        if (i != j) {
#pragma unroll
            for (int nt = 0; nt < 8; ++nt) {
#pragma unroll
                for (int j0 = 0; j0 < 2; ++j0) {
                    float v = acc[0][nt][j0] + acc[0][nt][j0 + 2]
                            + acc[1][nt][j0] + acc[1][nt][j0 + 2];
                    int col = wn * 64 + (nt >> 1) * 16 + (nt & 1) * 8
                            + (lane & 3) * 2 + j0;
                    red_c2[col * 33 + slot] = v;
                }
            }
        }
        __syncthreads();

        if (tid < BM) {
            slice[i * BM + tid] += red_r[tid * 2] + red_r[tid * 2 + 1];
            if (i != j) {
                float s = 0.f;
#pragma unroll
                for (int k = 0; k < 32; ++k) s += red_c2[tid * 33 + k];
                slice[j * BN + tid] += s;
            }
        }

        // advance tile coordinates
        i = ni;
        j = nj;
    }
}

// ---------------------------------------------------------------------------
// Kernel 3: per-row term + block reduce + last-block finalize (fused mean).
// Deterministic: the last block reads the fixed 16-element partial array in
// fixed order; the ticket counter self-resets for graph replay.
// ---------------------------------------------------------------------------
__global__ void __launch_bounds__(512) rowterm_final_kernel(float* __restrict__ out) {
    const float E2 = 7.38905609893065f;  // exp(2): diagonal of normalized sim
    int tid = threadIdx.x;
    int r = blockIdx.x * 512 + tid;
    float s = 0.f;
#pragma unroll 4
    for (int c = 0; c < NCTA; ++c) s += gx_slice[(size_t)c * NROWS + r];
    float term = logf(s - E2) - 2.0f * gx_pos[r & (BATCH - 1)];
#pragma unroll
    for (int o = 16; o > 0; o >>= 1)
        term += __shfl_xor_sync(0xffffffffu, term, o);
    __shared__ float sh[16];
    __shared__ bool is_last;
    if ((tid & 31) == 0) sh[tid >> 5] = term;
    __syncthreads();
    if (tid < 32) {
        float v = (tid < 16) ? sh[tid] : 0.f;
#pragma unroll
        for (int o = 8; o > 0; o >>= 1) v += __shfl_xor_sync(0xffffffffu, v, o);
        if (tid == 0) {
            gx_bsum[blockIdx.x] = v;
            __threadfence();
            int old = atomicAdd(&gx_ctr, 1);
            is_last = (old == NRBLK - 1);
        }
    }
    __syncthreads();
    if (is_last && tid < 32) {
        __threadfence();
        float v = (tid < NRBLK) ? gx_bsum[tid] : 0.f;
#pragma unroll
        for (int o = 8; o > 0; o >>= 1) v += __shfl_xor_sync(0xffffffffu, v, o);
        if (tid == 0) {
            out[0] = v * (1.0f / (float)NROWS);
            gx_ctr = 0;  // reset for next graph replay
        }
    }
}

// ---------------------------------------------------------------------------
extern "C" void kernel_launch(void* const* d_in, const int* in_sizes, int n_in,
                              void* d_out, int out_size) {
    const float* p1 = (const float*)d_in[0];
    const float* p2 = (const float*)d_in[1];
    float* out = (float*)d_out;

    l2norm_pos_kernel<<<BATCH / 8, 256>>>(p1, p2);

    cudaFuncSetAttribute((const void*)simexp_tri_kernel,
                         cudaFuncAttributeMaxDynamicSharedMemorySize, SM_TOTAL);
    simexp_tri_kernel<<<NCTA, 256, SM_TOTAL>>>();

    rowterm_final_kernel<<<NRBLK, 512>>>(out);
}